// round 4
// baseline (speedup 1.0000x reference)
#include <cuda_runtime.h>
#include <cstdint>
#include <cstddef>

// SDDMM: out[M,N] = x[M,N] * (y[M,K] @ z[K,N]),  M=N=8192, K=64, fp32.
// Persistent-band CTAs: each CTA stages y once and sweeps T_TILES N-tiles.
// Raw-f32 staged via cp.async (double-buffered z), cvt.rna.tf32 after LDS,
// mma.sync m16n8k8, epilogue transposes acc through the freed z buffer.

#define M_DIM 8192
#define N_DIM 8192
#define K_DIM 64
#define BM 128
#define BN 128
#define T_TILES 4

#define YS 68                       // y row stride (words): conflict-free frags
#define ZS 136                      // z row stride (words): conflict-free frags
#define EPS 68                      // epilogue row stride (words)
#define Y_WORDS (BM * YS)           // 8704
#define Z_WORDS (K_DIM * ZS)        // 8704 (== 8 warps * 16 * EPS)

#define SMEM_WORDS (Y_WORDS + 2 * Z_WORDS)
#define SMEM_BYTES (SMEM_WORDS * 4) // 104448 B -> 2 CTAs/SM

__device__ __forceinline__ uint32_t f2tf32(float f) {
    uint32_t r;
    asm("cvt.rna.tf32.f32 %0, %1;" : "=r"(r) : "f"(f));
    return r;
}
__device__ __forceinline__ uint32_t smem_u32(const void* p) {
    uint32_t a;
    asm("{ .reg .u64 t; cvta.to.shared.u64 t, %1; cvt.u32.u64 %0, t; }" : "=r"(a) : "l"(p));
    return a;
}
__device__ __forceinline__ void cp16(uint32_t dst, const void* src) {
    asm volatile("cp.async.cg.shared.global [%0], [%1], 16;" :: "r"(dst), "l"(src));
}
__device__ __forceinline__ void cp_commit() {
    asm volatile("cp.async.commit_group;" ::: "memory");
}
__device__ __forceinline__ void cp_wait_all() {
    asm volatile("cp.async.wait_group 0;" ::: "memory");
}

__global__ void __launch_bounds__(256, 2)
sddmm_pipe_kernel(const float* __restrict__ x,
                  const float* __restrict__ y,
                  const float* __restrict__ z,
                  float* __restrict__ out)
{
    extern __shared__ float smem[];
    float* ybuf = smem;                       // [128][68] raw f32
    float* zbuf[2] = { smem + Y_WORDS, smem + Y_WORDS + Z_WORDS }; // [64][136]

    const uint32_t sb = smem_u32(smem);
    const int tid  = threadIdx.x;
    const int bm   = blockIdx.y;
    const int bng  = blockIdx.x;              // N-group: tiles bng*T_TILES + t

    // ---- stage y (once) + z tile 0, both raw f32 via cp.async ----
    {
        const float* yg = y + (size_t)bm * BM * K_DIM;
        #pragma unroll
        for (int j = 0; j < 8; j++) {
            int ch = tid + j * 256;           // 16B chunk id over 128x16
            int r = ch >> 4, c = ch & 15;
            cp16(sb + (uint32_t)(r * YS + c * 4) * 4, yg + r * K_DIM + c * 4);
        }
        const float* zg = z + (size_t)(bng * T_TILES) * BN;
        const uint32_t zb0 = sb + Y_WORDS * 4;
        #pragma unroll
        for (int j = 0; j < 8; j++) {
            int ch = tid + j * 256;           // 16B chunk id over 64x32
            int k = ch >> 5, c = ch & 31;
            cp16(zb0 + (uint32_t)(k * ZS + c * 4) * 4, zg + (size_t)k * N_DIM + c * 4);
        }
        cp_commit();
    }

    const int warp = tid >> 5;
    const int lane = tid & 31;
    const int wm = (warp >> 1) * 32;          // 4 warps over M
    const int wn = (warp & 1) * 64;           // 2 warps over N
    const int g  = lane >> 2;
    const int ti = lane & 3;

    cp_wait_all();
    __syncthreads();

    int cur = 0;
    #pragma unroll 1
    for (int t = 0; t < T_TILES; t++) {
        const int bn = bng * T_TILES + t;

        // ---- prefetch z(t+1) into the other buffer ----
        if (t + 1 < T_TILES) {
            const float* zg = z + (size_t)(bn + 1) * BN;
            const uint32_t zbn = sb + (Y_WORDS + (1 - cur) * Z_WORDS) * 4;
            #pragma unroll
            for (int j = 0; j < 8; j++) {
                int ch = tid + j * 256;
                int k = ch >> 5, c = ch & 31;
                cp16(zbn + (uint32_t)(k * ZS + c * 4) * 4, zg + (size_t)k * N_DIM + c * 4);
            }
            cp_commit();
        }

        // ---- MMA mainloop: raw LDS + cvt.rna -> tf32 frags ----
        const float* zc = zbuf[cur];
        float acc[2][8][4];
        #pragma unroll
        for (int a = 0; a < 2; a++)
            #pragma unroll
            for (int b = 0; b < 8; b++)
                #pragma unroll
                for (int q = 0; q < 4; q++) acc[a][b][q] = 0.f;

        #pragma unroll
        for (int ks = 0; ks < K_DIM / 8; ks++) {
            uint32_t A[2][4];
            #pragma unroll
            for (int mt = 0; mt < 2; mt++) {
                const float* base = ybuf + (wm + mt * 16 + g) * YS + ks * 8 + ti;
                A[mt][0] = f2tf32(base[0]);
                A[mt][1] = f2tf32(base[8 * YS]);
                A[mt][2] = f2tf32(base[4]);
                A[mt][3] = f2tf32(base[8 * YS + 4]);
            }
            uint32_t B[8][2];
            #pragma unroll
            for (int nt = 0; nt < 8; nt++) {
                const float* base = zc + (ks * 8 + ti) * ZS + wn + nt * 8 + g;
                B[nt][0] = f2tf32(base[0]);
                B[nt][1] = f2tf32(base[4 * ZS]);
            }
            #pragma unroll
            for (int mt = 0; mt < 2; mt++)
                #pragma unroll
                for (int nt = 0; nt < 8; nt++)
                    asm volatile(
                        "mma.sync.aligned.m16n8k8.row.col.f32.tf32.tf32.f32 "
                        "{%0,%1,%2,%3}, {%4,%5,%6,%7}, {%8,%9}, {%0,%1,%2,%3};"
                        : "+f"(acc[mt][nt][0]), "+f"(acc[mt][nt][1]),
                          "+f"(acc[mt][nt][2]), "+f"(acc[mt][nt][3])
                        : "r"(A[mt][0]), "r"(A[mt][1]), "r"(A[mt][2]), "r"(A[mt][3]),
                          "r"(B[nt][0]), "r"(B[nt][1]));
        }

        // all warps done reading z[cur]; reuse it as the transpose buffer
        __syncthreads();

        // ---- epilogue: 2 halves (mt), warp-private 16x68 region in z[cur] ----
        float* ep = zbuf[cur] + warp * (16 * EPS);
        const int sub = lane >> 4;
        const int c4  = (lane & 15) << 2;

        #pragma unroll
        for (int mt = 0; mt < 2; mt++) {
            #pragma unroll
            for (int pair = 0; pair < 2; pair++) {
                const int lr = pair * 8 + g;
                const int sw = 4 * (lr & 3);
                float* rowp = ep + lr * EPS;
                #pragma unroll
                for (int nt = 0; nt < 8; nt++) {
                    const int lc = (nt * 8 + 2 * ti + sw) & 63;
                    float2 v;
                    v.x = acc[mt][nt][2 * pair + 0];
                    v.y = acc[mt][nt][2 * pair + 1];
                    *reinterpret_cast<float2*>(rowp + lc) = v;
                }
            }
            __syncwarp();

            const size_t grow = (size_t)(bm * BM + wm + mt * 16);
            const int    gcol = bn * BN + wn + c4;
            #pragma unroll
            for (int it = 0; it < 8; it++) {
                const int lr = it * 2 + sub;
                const int pc = (c4 + 4 * (lr & 3)) & 63;
                const float4 a = *reinterpret_cast<const float4*>(ep + lr * EPS + pc);
                const size_t goff = (grow + lr) * (size_t)N_DIM + gcol;
                const float4 xv = *reinterpret_cast<const float4*>(x + goff);
                float4 o;
                o.x = xv.x * a.x;
                o.y = xv.y * a.y;
                o.z = xv.z * a.z;
                o.w = xv.w * a.w;
                *reinterpret_cast<float4*>(out + goff) = o;
            }
            __syncwarp();
        }

        if (t + 1 < T_TILES) cp_wait_all();   // z(t+1) landed
        __syncthreads();                       // epi done + z[nxt] visible
        cur = 1 - cur;
    }
}

extern "C" void kernel_launch(void* const* d_in, const int* in_sizes, int n_in,
                              void* d_out, int out_size)
{
    const float* x = (const float*)d_in[0];
    const float* y = (const float*)d_in[1];
    const float* z = (const float*)d_in[2];
    float* out = (float*)d_out;
    (void)in_sizes; (void)n_in; (void)out_size;

    cudaFuncSetAttribute(sddmm_pipe_kernel,
                         cudaFuncAttributeMaxDynamicSharedMemorySize, SMEM_BYTES);

    dim3 grid(N_DIM / (BN * T_TILES), M_DIM / BM);   // (16, 64)
    sddmm_pipe_kernel<<<grid, 256, SMEM_BYTES>>>(x, y, z, out);
}